// round 16
// baseline (speedup 1.0000x reference)
#include <cuda_runtime.h>
#include <cstdint>
#include <cstddef>

// Problem dims (fixed)
#define BB    256
#define TT    64
#define DIN   1024
#define HH    1024
#define EE    256
#define VV    8192
#define FOURH 4096
#define BK    16
#define SR    20              // smem row stride (floats); 80B rows -> LDSM conflict-free
#define MSL   (128 * SR)
#define STAGE_F (4 * MSL)     // floats per pipeline stage
#define SMEM_B  (2 * STAGE_F * 4)   // dynamic smem bytes (81920)

// ---------------- scratch ----------------------------------------------------
__device__ float g_h[BB * HH];
__device__ float g_c[BB * HH];
__device__ float g_XW[BB * TT * FOURH];   // packed x_t @ W_ih_x^T
__device__ float g_EW[VV * FOURH];        // emb @ W_ih_e^T
__device__ float g_I0[FOURH];             // init_tensor @ W_ih_e^T
__device__ int   g_amax[BB];
__device__ float g_P[8][128][FOURH];      // gates partials (8-way max)
__device__ float g_logP[4][128][VV];      // logits split-K partials (4-way max)
__device__ int   g_lcnt[128];             // combine counters (zero-init)
__device__ int   g_fcnt[2];
__device__ float g_pval[BB * 256];
__device__ int   g_pidx[BB * 256];
__device__ int   g_off[BB];
__device__ int   g_nb[TT];
__device__ int   g_nrows;
__device__ int   g_rbt[BB * TT];          // packed row -> (b<<6)|t

// ---------------- helpers -----------------------------------------------------
__device__ __forceinline__ float tf32r(float x) {
    uint32_t u;
    asm("cvt.rna.tf32.f32 %0, %1;" : "=r"(u) : "f"(x));
    return __uint_as_float(u);
}
__device__ __forceinline__ void split4(float4 v, float4& h, float4& l) {
    h.x = tf32r(v.x); h.y = tf32r(v.y); h.z = tf32r(v.z); h.w = tf32r(v.w);
    l.x = tf32r(v.x - h.x); l.y = tf32r(v.y - h.y);
    l.z = tf32r(v.z - h.z); l.w = tf32r(v.w - h.w);
}
__device__ __forceinline__ void mma8(float* c, const uint32_t* a, const uint32_t* b) {
    asm volatile(
        "mma.sync.aligned.m16n8k8.row.col.f32.tf32.tf32.f32 "
        "{%0,%1,%2,%3}, {%4,%5,%6,%7}, {%8,%9}, {%0,%1,%2,%3};"
        : "+f"(c[0]), "+f"(c[1]), "+f"(c[2]), "+f"(c[3])
        : "r"(a[0]), "r"(a[1]), "r"(a[2]), "r"(a[3]), "r"(b[0]), "r"(b[1]));
}
__device__ __forceinline__ void ldsm4(uint32_t* r, uint32_t addr) {
    asm volatile("ldmatrix.sync.aligned.m8n8.x4.shared.b16 {%0,%1,%2,%3}, [%4];"
        : "=r"(r[0]), "=r"(r[1]), "=r"(r[2]), "=r"(r[3]) : "r"(addr));
}
__device__ __forceinline__ float sigm(float x) { return 1.0f / (1.0f + expf(-x)); }

__device__ __forceinline__ void sts_split(float* S, int tid,
                                          const float4* av, const float4* bv) {
    float* AHI = S;
    float* ALO = S + MSL;
    float* BHI = S + 2 * MSL;
    float* BLO = S + 3 * MSL;
#pragma unroll
    for (int j = 0; j < 2; j++) {
        int idx = j * 256 + tid;
        int row = idx >> 2, kq = idx & 3;
        int o = row * SR + kq * 4;
        float4 h, l;
        split4(av[j], h, l);
        *(float4*)&AHI[o] = h; *(float4*)&ALO[o] = l;
        split4(bv[j], h, l);
        *(float4*)&BHI[o] = h; *(float4*)&BLO[o] = l;
    }
}

// 3-pass fragment compute; A via ldsm.x4, B via PAIRED ldsm.x4 (2 n-groups/ld).
__device__ __forceinline__ void mma_block(uint32_t sbase, uint32_t aoff, uint32_t boff,
                                          float acc[4][4][4]) {
    const uint32_t aHi = sbase + aoff;
    const uint32_t bHi = sbase + 2u * (MSL * 4u) + boff;
#pragma unroll
    for (int ks = 0; ks < 2; ks++) {
        uint32_t ka = aHi + ks * 32u;   // +8 floats per ks
        uint32_t kb = bHi + ks * 32u;
        uint32_t af[4][4], bf[4][2];
        // pass 1: ah * bh
#pragma unroll
        for (int m = 0; m < 4; m++) ldsm4(af[m], ka + m * (16u * SR * 4u));
#pragma unroll
        for (int np = 0; np < 2; np++) ldsm4(bf[2 * np], kb + np * (16u * SR * 4u));
#pragma unroll
        for (int m = 0; m < 4; m++)
#pragma unroll
            for (int n = 0; n < 4; n++) mma8(acc[m][n], af[m], bf[n]);
        // pass 2: ah * bl
#pragma unroll
        for (int np = 0; np < 2; np++)
            ldsm4(bf[2 * np], kb + (MSL * 4u) + np * (16u * SR * 4u));
#pragma unroll
        for (int m = 0; m < 4; m++)
#pragma unroll
            for (int n = 0; n < 4; n++) mma8(acc[m][n], af[m], bf[n]);
        // pass 3: al * bh
#pragma unroll
        for (int m = 0; m < 4; m++) ldsm4(af[m], ka + (MSL * 4u) + m * (16u * SR * 4u));
#pragma unroll
        for (int np = 0; np < 2; np++) ldsm4(bf[2 * np], kb + np * (16u * SR * 4u));
#pragma unroll
        for (int m = 0; m < 4; m++)
#pragma unroll
            for (int n = 0; n < 4; n++) mma8(acc[m][n], af[m], bf[n]);
    }
}

#define ACC_ZERO(acc)                                   \
    _Pragma("unroll")                                   \
    for (int a_ = 0; a_ < 4; a_++)                      \
        _Pragma("unroll")                               \
        for (int b_ = 0; b_ < 4; b_++)                  \
            _Pragma("unroll")                           \
            for (int c_ = 0; c_ < 4; c_++) acc[a_][b_][c_] = 0.0f;

// Per-thread ldmatrix address offsets (bytes) within a stage.
#define LDSM_OFFSETS()                                                        \
    const int L_ = tid & 31;                                                  \
    const uint32_t aoff = ((uint32_t)((L_ & 15) + wm * 64) * SR) * 4u +       \
                          (uint32_t)(L_ >> 4) * 16u;                          \
    const uint32_t boff = ((uint32_t)((((L_ >> 4) & 1) * 8) + (L_ & 7) + wn * 32) * SR) * 4u + \
                          (uint32_t)((L_ >> 3) & 1) * 16u;

// Double-buffered mainloop: 1 sync per chunk, STS overlapped with MMA.
#define GEMM_PIPELINE(S, sb, nch, LOADG)                      \
    LOADG(0);                                                 \
    sts_split(S, tid, av, bv);                                \
    __syncthreads();                                          \
    for (int i = 0; i < (nch); i++) {                         \
        bool more_ = (i + 1 < (nch));                         \
        if (more_) LOADG(i + 1);                              \
        mma_block((sb) + (uint32_t)(i & 1) * (STAGE_F * 4u), aoff, boff, acc); \
        if (more_) sts_split((S) + ((i + 1) & 1) * STAGE_F, tid, av, bv); \
        __syncthreads();                                      \
    }

// ---------------- init / scan -------------------------------------------------
__global__ void k_init() {
    int idx = blockIdx.x * 256 + threadIdx.x;
    if (idx < BB * HH) { g_h[idx] = 0.0f; g_c[idx] = 0.0f; }
}
__global__ void k_scan(const int* __restrict__ seq_lens) {
    int tid = threadIdx.x;   // 256
    if (tid == 0) {
        int acc = 0;
        for (int b = 0; b < BB; b++) { g_off[b] = acc; acc += seq_lens[b]; }
        g_nrows = acc;
    }
    if (tid < TT) {
        int c = 0;
        for (int b = 0; b < BB; b++) c += (seq_lens[b] > tid) ? 1 : 0;
        g_nb[tid] = c;
    }
    __syncthreads();
    {
        int b = tid;
        int o = g_off[b], len = seq_lens[b];
        for (int t = 0; t < len; t++) g_rbt[o + t] = (b << 6) | t;
    }
}
__global__ void k_I0(const float* __restrict__ init_t,
                     const float* __restrict__ W_ih) {
    int j = blockIdx.x * 256 + threadIdx.x;   // 4096
    const float* w = W_ih + (size_t)j * (DIN + EE) + DIN;
    float s = 0.0f;
    for (int e = 0; e < EE; e++) s += init_t[e] * w[e];
    g_I0[j] = s;
}

// ================= Phase A (fused): EW (by<64) and XW (by>=64) ================
__global__ __launch_bounds__(256, 2)
void kA(const float* __restrict__ enc, const float* __restrict__ emb,
        const float* __restrict__ W_ih) {
    extern __shared__ float S[];
    const uint32_t sb = (uint32_t)__cvta_generic_to_shared(S);
    const int tid = threadIdx.x;
    const int wid = tid >> 5;
    const int wm  = wid >> 2, wn = wid & 3;
    const int g   = (tid & 31) >> 2, tig = tid & 3;
    const int kq  = tid & 3;
    LDSM_OFFSETS()

    const int bn = blockIdx.x * 128;
    float acc[4][4][4];
    ACC_ZERO(acc)
    float4 av[2], bv[2];

    // unified parameter decode (single pipeline instantiation)
    const bool isE = (blockIdx.y < VV / 128);
    int bm;
    int nch;
    const float* pa[2];
    const float* pb[2];
    if (isE) {
        bm = blockIdx.y * 128;
        nch = EE / BK;
#pragma unroll
        for (int j = 0; j < 2; j++) {
            int row = ((j * 256 + tid) >> 2);
            pa[j] = emb + (size_t)(bm + row) * EE;
            pb[j] = W_ih + (size_t)(bn + row) * (DIN + EE) + DIN;
        }
    } else {
        bm = (blockIdx.y - VV / 128) * 128;
        if (bm >= g_nrows) return;
        nch = DIN / BK;
#pragma unroll
        for (int j = 0; j < 2; j++) {
            int row = ((j * 256 + tid) >> 2);
            int bt = g_rbt[bm + row];
            int b = bt >> 6, t = bt & 63;
            pa[j] = enc + ((size_t)b * TT + t) * DIN;
            pb[j] = W_ih + (size_t)(bn + row) * (DIN + EE);
        }
    }

#define LG(ch)                                                    \
    { int kkb = (ch) * BK + kq * 4;                               \
      _Pragma("unroll")                                           \
      for (int j = 0; j < 2; j++) {                               \
          av[j] = *(const float4*)(pa[j] + kkb);                  \
          bv[j] = *(const float4*)(pb[j] + kkb); } }
    GEMM_PIPELINE(S, sb, nch, LG)
#undef LG

    float* dst = isE ? g_EW : g_XW;
#pragma unroll
    for (int m = 0; m < 4; m++) {
        int lr0 = wm * 64 + m * 16 + g, lr1 = lr0 + 8;
#pragma unroll
        for (int n = 0; n < 4; n++) {
            int col = bn + wn * 32 + n * 8 + 2 * tig;
            *(float2*)&dst[(size_t)(bm + lr0) * FOURH + col] =
                make_float2(acc[m][n][0], acc[m][n][1]);
            *(float2*)&dst[(size_t)(bm + lr1) * FOURH + col] =
                make_float2(acc[m][n][2], acc[m][n][3]);
        }
    }
}

// ================= logits epilogue helper =====================================
__device__ __forceinline__ void logits_out(
    float acc[4][4][4], int own, int slot0, int nop,
    const float* __restrict__ lin_b, const int* __restrict__ seq_lens,
    float* __restrict__ out, int t,
    int bm, int bn, int wm, int wn, int g, int tig, int bx) {
#pragma unroll
    for (int half = 0; half < 2; half++) {
#pragma unroll
        for (int mt = 0; mt < 4; mt++) {
            int lr = wm * 64 + mt * 16 + g + half * 8;
            int gm = bm + lr;
            int len = seq_lens[gm];
            bool wr = (t < len);
            float* orow = out + (size_t)(g_off[gm] + t) * VV;

            float bvv = -3.4e38f;
            int   bii = 0;
#pragma unroll
            for (int nt = 0; nt < 4; nt++) {
                int col = bn + wn * 32 + nt * 8 + 2 * tig;
                float a0 = acc[mt][nt][half * 2 + 0];
                float a1 = acc[mt][nt][half * 2 + 1];
                float v0, v1;
                if (nop == 2) {
                    int oth = (own == slot0) ? slot0 + 1 : slot0;
                    v0 = a0 + __ldcg(&g_logP[oth][lr][col]);
                    v1 = a1 + __ldcg(&g_logP[oth][lr][col + 1]);
                } else {
                    float x0 = (own == 0) ? a0 : __ldcg(&g_logP[0][lr][col]);
                    float x1 = (own == 1) ? a0 : __ldcg(&g_logP[1][lr][col]);
                    float x2 = (own == 2) ? a0 : __ldcg(&g_logP[2][lr][col]);
                    float x3 = (own == 3) ? a0 : __ldcg(&g_logP[3][lr][col]);
                    v0 = (x0 + x1) + (x2 + x3);
                    float y0 = (own == 0) ? a1 : __ldcg(&g_logP[0][lr][col + 1]);
                    float y1 = (own == 1) ? a1 : __ldcg(&g_logP[1][lr][col + 1]);
                    float y2 = (own == 2) ? a1 : __ldcg(&g_logP[2][lr][col + 1]);
                    float y3 = (own == 3) ? a1 : __ldcg(&g_logP[3][lr][col + 1]);
                    v1 = (y0 + y1) + (y2 + y3);
                }
                v0 += lin_b[col];
                v1 += lin_b[col + 1];
                if (wr) *(float2*)&orow[col] = make_float2(v0, v1);
                if (v0 > bvv) { bvv = v0; bii = col; }
                if (v1 > bvv) { bvv = v1; bii = col + 1; }
            }
#pragma unroll
            for (int off = 1; off < 4; off <<= 1) {
                float ov = __shfl_xor_sync(0xffffffffu, bvv, off, 4);
                int   oi = __shfl_xor_sync(0xffffffffu, bii, off, 4);
                if (ov > bvv || (ov == bvv && oi < bii)) { bvv = ov; bii = oi; }
            }
            if (tig == 0) {
                int slot = bx * 4 + wn;
                g_pval[(size_t)gm * 256 + slot] = bvv;
                g_pidx[(size_t)gm * 256 + slot] = bii;
            }
        }
    }
}

// ================= fused kernel: logits(t) || gates(t+1), ONE pipeline ========
// Even CTAs = logits(t), odd CTAs = gates(t+1). Both halves share a single
// GEMM pipeline instantiation (same A source g_h, same B addressing); only
// the parameter decode and the epilogue differ.
__global__ __launch_bounds__(256, 2)
void k_lg(const float* __restrict__ W_hh,
          const float* __restrict__ lin_W,
          const float* __restrict__ lin_b,
          const int*   __restrict__ seq_lens,
          float* __restrict__ out,
          int t) {
    extern __shared__ float S[];
    const uint32_t sbda = (uint32_t)__cvta_generic_to_shared(S);
    const int cta  = blockIdx.x;
    const int kind = cta & 1;          // 1 = gates(t+1), 0 = logits(t)
    const int idx  = cta >> 1;         // 0..255

    const int tid = threadIdx.x;
    const int wid = tid >> 5;
    const int wm  = wid >> 2, wn = wid & 3;
    const int g   = (tid & 31) >> 2, tig = tid & 3;
    const int kq  = tid & 3;
    LDSM_OFFSETS()

    // ---- unified parameter decode ----
    int bm, kbeg, nch, bn;
    const float* Bb;
    int slot = 0;                                  // gates
    int own = 0, slot0 = 0, nop = 0, cidx = 0, cthr = 0, fi = 0, bx = 0;  // logits

    if (kind) {
        if (t + 1 >= TT) return;                   // last step: no gates half
        const int nbt = g_nb[t + 1];
        int bx_ = idx & 31, by = (idx >> 5) & 3, bz = (idx >> 7) & 1;
        if (nbt > 128) {
            bm = bz * 128; kbeg = by * (HH / 4); nch = (HH / 4) / BK;  // 16
            slot = bz * 4 + by;
        } else {
            bm = 0;
            int ks = by * 2 + bz;
            kbeg = ks * (HH / 8); nch = (HH / 8) / BK;                // 8
            slot = ks;
        }
        bn = bx_ * 128;
        Bb = W_hh;
    } else {
        const int nbt = g_nb[t];
        const bool split = (nbt <= 128);
        bx = idx & 63;
        int by = (idx >> 6) & 1, bz = (idx >> 7) & 1;
        if (!split) {
            bm = bz * 128; kbeg = by * (HH / 2); nch = (HH / 2) / BK; // 32
            own = bz * 2 + by; slot0 = bz * 2; nop = 2;
            cidx = bx * 2 + bz; cthr = 2; fi = bz;
        } else {
            int q = by * 2 + bz;
            bm = 0; kbeg = q * (HH / 4); nch = (HH / 4) / BK;         // 16
            own = q; slot0 = 0; nop = 4;
            cidx = bx; cthr = 4; fi = 0;
        }
        bn = bx * 128;
        Bb = lin_W;
    }

    const float* pa[2];
    const float* pb[2];
#pragma unroll
    for (int j = 0; j < 2; j++) {
        int row = ((j * 256 + tid) >> 2);
        pa[j] = g_h + (size_t)(bm + row) * HH + kbeg;
        pb[j] = Bb + (size_t)(bn + row) * HH + kbeg;
    }

    float acc[4][4][4];
    ACC_ZERO(acc)
    float4 av[2], bv[2];
#define LG(ch)                                                    \
    { int kkb = (ch) * BK + kq * 4;                               \
      _Pragma("unroll")                                           \
      for (int j = 0; j < 2; j++) {                               \
          av[j] = *(const float4*)(pa[j] + kkb);                  \
          bv[j] = *(const float4*)(pb[j] + kkb); } }
    GEMM_PIPELINE(S, sbda, nch, LG)
#undef LG

    if (kind) {
        // ---- gates epilogue: partial to g_P[slot] ----
#pragma unroll
        for (int m = 0; m < 4; m++) {
            int lr0 = wm * 64 + m * 16 + g, lr1 = lr0 + 8;
#pragma unroll
            for (int n = 0; n < 4; n++) {
                int col = bn + wn * 32 + n * 8 + 2 * tig;
                *(float2*)&g_P[slot][lr0][col] =
                    make_float2(acc[m][n][0], acc[m][n][1]);
                *(float2*)&g_P[slot][lr1][col] =
                    make_float2(acc[m][n][2], acc[m][n][3]);
            }
        }
        return;
    }

    // ---- logits epilogue: store partial, combine, fused argmax ----
#pragma unroll
    for (int half = 0; half < 2; half++)
#pragma unroll
        for (int mt = 0; mt < 4; mt++) {
            int lr = wm * 64 + mt * 16 + g + half * 8;
#pragma unroll
            for (int nt = 0; nt < 4; nt++) {
                int col = bn + wn * 32 + nt * 8 + 2 * tig;
                *(float2*)&g_logP[own][lr][col] =
                    make_float2(acc[mt][nt][half * 2], acc[mt][nt][half * 2 + 1]);
            }
        }
    __syncthreads();
    __shared__ int swin;
    if (tid == 0) {
        __threadfence();
        int old = atomicAdd(&g_lcnt[cidx], 1);
        swin = (old == cthr - 1);
        if (old == cthr - 1) g_lcnt[cidx] = 0;
    }
    __syncthreads();
    if (!swin) return;
    __threadfence();
    logits_out(acc, own, slot0, nop, lin_b, seq_lens, out, t,
               bm, bn, wm, wn, g, tig, bx);

    __syncthreads();
    __shared__ int lastf;
    if (tid == 0) {
        __threadfence();
        int old = atomicAdd(&g_fcnt[fi], 1);
        lastf = (old == 63);
        if (old == 63) g_fcnt[fi] = 0;
    }
    __syncthreads();
    if (!lastf) return;
    __threadfence();

    {
        int wv = tid >> 5, lane = tid & 31;
#pragma unroll 1
        for (int i = 0; i < 16; i++) {
            int b = bm + wv * 16 + i;
            float v = -3.4e38f;
            int   bi = 0x7fffffff;
            for (int s = lane; s < 256; s += 32) {
                float pv = __ldcg(&g_pval[(size_t)b * 256 + s]);
                int   pi = __ldcg(&g_pidx[(size_t)b * 256 + s]);
                if (pv > v || (pv == v && pi < bi)) { v = pv; bi = pi; }
            }
#pragma unroll
            for (int off = 16; off; off >>= 1) {
                float ov = __shfl_xor_sync(0xffffffffu, v, off);
                int   oi = __shfl_xor_sync(0xffffffffu, bi, off);
                if (ov > v || (ov == v && oi < bi)) { v = ov; bi = oi; }
            }
            if (lane == 0) g_amax[b] = bi;
        }
    }
}

// ---------------- LSTM cell: float4-vectorized (4 j-elements / thread) --------
__global__ void k_cell(const float* __restrict__ b_ih,
                       const float* __restrict__ b_hh,
                       const int* __restrict__ seq_lens,
                       int t) {
    int v = blockIdx.x * 256 + threadIdx.x;   // 0..65535
    int b = v >> 8;
    int j = (v & 255) * 4;
    int nbt = g_nb[t];
    if (nbt <= 128 && b >= 128) return;
    if (t >= seq_lens[b]) return;

    float4 gate[4];
#pragma unroll
    for (int q = 0; q < 4; q++) {
        int jj = q * 1024 + j;
        float4 r;
        if (t == 0) {
            r = make_float4(0.f, 0.f, 0.f, 0.f);
        } else if (nbt > 128) {
            int s0 = (b >> 7) * 4, lr = b & 127;
            float4 p0 = *(const float4*)&g_P[s0][lr][jj];
            float4 p1 = *(const float4*)&g_P[s0 + 1][lr][jj];
            float4 p2 = *(const float4*)&g_P[s0 + 2][lr][jj];
            float4 p3 = *(const float4*)&g_P[s0 + 3][lr][jj];
            r.x = (p0.x + p1.x) + (p2.x + p3.x);
            r.y = (p0.y + p1.y) + (p2.y + p3.y);
            r.z = (p0.z + p1.z) + (p2.z + p3.z);
            r.w = (p0.w + p1.w) + (p2.w + p3.w);
        } else {
            float4 p0 = *(const float4*)&g_P[0][b][jj];
            float4 p1 = *(const float4*)&g_P[1][b][jj];
            float4 p2 = *(const float4*)&g_P[2][b][jj];
            float4 p3 = *(const float4*)&g_P[3][b][jj];
            float4 p4 = *(const float4*)&g_P[4][b][jj];
            float4 p5 = *(const float4*)&g_P[5][b][jj];
            float4 p6 = *(const float4*)&g_P[6][b][jj];
            float4 p7 = *(const float4*)&g_P[7][b][jj];
            r.x = ((p0.x + p1.x) + (p2.x + p3.x)) + ((p4.x + p5.x) + (p6.x + p7.x));
            r.y = ((p0.y + p1.y) + (p2.y + p3.y)) + ((p4.y + p5.y) + (p6.y + p7.y));
            r.z = ((p0.z + p1.z) + (p2.z + p3.z)) + ((p4.z + p5.z) + (p6.z + p7.z));
            r.w = ((p0.w + p1.w) + (p2.w + p3.w)) + ((p4.w + p5.w) + (p6.w + p7.w));
        }
        gate[q] = r;
    }
    const float* XW = g_XW + (size_t)(g_off[b] + t) * FOURH;
    const float* EW = (t == 0) ? g_I0 : g_EW + (size_t)g_amax[b] * FOURH;
    size_t cidx = (size_t)b * HH + j;
    float4 cc = *(const float4*)&g_c[cidx];
    float4 ho, co;
#pragma unroll
    for (int e = 0; e < 4; e++) {
        int je = j + e;
        float gi = (&gate[0].x)[e] + XW[je]        + EW[je]        + b_ih[je]        + b_hh[je];
        float gf = (&gate[1].x)[e] + XW[1024 + je] + EW[1024 + je] + b_ih[1024 + je] + b_hh[1024 + je];
        float gg = (&gate[2].x)[e] + XW[2048 + je] + EW[2048 + je] + b_ih[2048 + je] + b_hh[2048 + je];
        float go = (&gate[3].x)[e] + XW[3072 + je] + EW[3072 + je] + b_ih[3072 + je] + b_hh[3072 + je];
        float c = sigm(gf) * (&cc.x)[e] + sigm(gi) * tanhf(gg);
        float h = sigm(go) * tanhf(c);
        (&co.x)[e] = c;
        (&ho.x)[e] = h;
    }
    *(float4*)&g_c[cidx] = co;
    *(float4*)&g_h[cidx] = ho;
}

// ---------------- launch ------------------------------------------------------
extern "C" void kernel_launch(void* const* d_in, const int* in_sizes, int n_in,
                              void* d_out, int out_size) {
    const float* enc      = (const float*)d_in[0];
    const float* emb      = (const float*)d_in[1];
    const float* init_t   = (const float*)d_in[2];
    const float* W_ih     = (const float*)d_in[3];
    const float* W_hh     = (const float*)d_in[4];
    const float* b_ih     = (const float*)d_in[5];
    const float* b_hh     = (const float*)d_in[6];
    const float* lin_W    = (const float*)d_in[7];
    const float* lin_b    = (const float*)d_in[8];
    const int*   seq_lens = (const int*)d_in[9];
    float*       out      = (float*)d_out;

    cudaFuncSetAttribute(kA,   cudaFuncAttributeMaxDynamicSharedMemorySize, SMEM_B);
    cudaFuncSetAttribute(k_lg, cudaFuncAttributeMaxDynamicSharedMemorySize, SMEM_B);

    k_init<<<(BB * HH + 255) / 256, 256>>>();
    k_scan<<<1, 256>>>(seq_lens);
    k_I0<<<FOURH / 256, 256>>>(init_t, W_ih);
    kA<<<dim3(32, VV / 128 + (BB * TT) / 128), 256, SMEM_B>>>(enc, emb, W_ih);

    // t = 0: h(0)==0, gates GEMM skipped (cell uses zero-gates path).
    k_cell<<<BB * HH / 1024, 256>>>(b_ih, b_hh, seq_lens, 0);

    for (int t = 0; t < TT - 1; t++) {
        // fused: logits(t) on even CTAs, gates(t+1) on odd CTAs — independent.
        k_lg<<<512, 256, SMEM_B>>>(W_hh, lin_W, lin_b, seq_lens, out, t);
        k_cell<<<BB * HH / 1024, 256>>>(b_ih, b_hh, seq_lens, t + 1);
    }
    // final logits (gates half self-disables at t+1 == TT)
    k_lg<<<512, 256, SMEM_B>>>(W_hh, lin_W, lin_b, seq_lens, out, TT - 1);
}

// round 17
// speedup vs baseline: 1.0918x; 1.0918x over previous
#include <cuda_runtime.h>
#include <cstdint>
#include <cstddef>

// Problem dims (fixed)
#define BB    256
#define TT    64
#define DIN   1024
#define HH    1024
#define EE    256
#define VV    8192
#define FOURH 4096
#define BK    16
#define SR    20              // smem row stride (floats); 80B rows -> LDSM conflict-free
#define MSL   (128 * SR)
#define STAGE_F (4 * MSL)     // floats per pipeline stage
#define SMEM_B  (2 * STAGE_F * 4)   // dynamic smem bytes (81920)

// ---------------- scratch ----------------------------------------------------
__device__ float g_h[BB * HH];
__device__ float g_c[BB * HH];
__device__ float g_XW[BB * TT * FOURH];   // packed x_t @ W_ih_x^T
__device__ float g_EW[VV * FOURH];        // emb @ W_ih_e^T
__device__ float g_I0[FOURH];             // init_tensor @ W_ih_e^T
__device__ float g_P[8][128][FOURH];      // gates partials (8-way max)
__device__ float g_logP[4][128][VV];      // logits split-K partials (4-way max)
__device__ int   g_off[BB];
__device__ int   g_nb[TT];
__device__ int   g_nrows;
__device__ int   g_rbt[BB * TT];          // packed row -> (b<<6)|t

// ---------------- helpers -----------------------------------------------------
__device__ __forceinline__ float tf32r(float x) {
    uint32_t u;
    asm("cvt.rna.tf32.f32 %0, %1;" : "=r"(u) : "f"(x));
    return __uint_as_float(u);
}
__device__ __forceinline__ void split4(float4 v, float4& h, float4& l) {
    h.x = tf32r(v.x); h.y = tf32r(v.y); h.z = tf32r(v.z); h.w = tf32r(v.w);
    l.x = tf32r(v.x - h.x); l.y = tf32r(v.y - h.y);
    l.z = tf32r(v.z - h.z); l.w = tf32r(v.w - h.w);
}
__device__ __forceinline__ void mma8(float* c, const uint32_t* a, const uint32_t* b) {
    asm volatile(
        "mma.sync.aligned.m16n8k8.row.col.f32.tf32.tf32.f32 "
        "{%0,%1,%2,%3}, {%4,%5,%6,%7}, {%8,%9}, {%0,%1,%2,%3};"
        : "+f"(c[0]), "+f"(c[1]), "+f"(c[2]), "+f"(c[3])
        : "r"(a[0]), "r"(a[1]), "r"(a[2]), "r"(a[3]), "r"(b[0]), "r"(b[1]));
}
__device__ __forceinline__ void ldsm4(uint32_t* r, uint32_t addr) {
    asm volatile("ldmatrix.sync.aligned.m8n8.x4.shared.b16 {%0,%1,%2,%3}, [%4];"
        : "=r"(r[0]), "=r"(r[1]), "=r"(r[2]), "=r"(r[3]) : "r"(addr));
}
__device__ __forceinline__ float sigm(float x) { return 1.0f / (1.0f + expf(-x)); }

__device__ __forceinline__ void sts_split(float* S, int tid,
                                          const float4* av, const float4* bv) {
    float* AHI = S;
    float* ALO = S + MSL;
    float* BHI = S + 2 * MSL;
    float* BLO = S + 3 * MSL;
#pragma unroll
    for (int j = 0; j < 2; j++) {
        int idx = j * 256 + tid;
        int row = idx >> 2, kq = idx & 3;
        int o = row * SR + kq * 4;
        float4 h, l;
        split4(av[j], h, l);
        *(float4*)&AHI[o] = h; *(float4*)&ALO[o] = l;
        split4(bv[j], h, l);
        *(float4*)&BHI[o] = h; *(float4*)&BLO[o] = l;
    }
}

// 3-pass fragment compute; A via ldsm.x4, B via PAIRED ldsm.x4 (2 n-groups/ld).
__device__ __forceinline__ void mma_block(uint32_t sbase, uint32_t aoff, uint32_t boff,
                                          float acc[4][4][4]) {
    const uint32_t aHi = sbase + aoff;
    const uint32_t bHi = sbase + 2u * (MSL * 4u) + boff;
#pragma unroll
    for (int ks = 0; ks < 2; ks++) {
        uint32_t ka = aHi + ks * 32u;   // +8 floats per ks
        uint32_t kb = bHi + ks * 32u;
        uint32_t af[4][4], bf[4][2];
        // pass 1: ah * bh
#pragma unroll
        for (int m = 0; m < 4; m++) ldsm4(af[m], ka + m * (16u * SR * 4u));
#pragma unroll
        for (int np = 0; np < 2; np++) ldsm4(bf[2 * np], kb + np * (16u * SR * 4u));
#pragma unroll
        for (int m = 0; m < 4; m++)
#pragma unroll
            for (int n = 0; n < 4; n++) mma8(acc[m][n], af[m], bf[n]);
        // pass 2: ah * bl
#pragma unroll
        for (int np = 0; np < 2; np++)
            ldsm4(bf[2 * np], kb + (MSL * 4u) + np * (16u * SR * 4u));
#pragma unroll
        for (int m = 0; m < 4; m++)
#pragma unroll
            for (int n = 0; n < 4; n++) mma8(acc[m][n], af[m], bf[n]);
        // pass 3: al * bh
#pragma unroll
        for (int m = 0; m < 4; m++) ldsm4(af[m], ka + (MSL * 4u) + m * (16u * SR * 4u));
#pragma unroll
        for (int np = 0; np < 2; np++) ldsm4(bf[2 * np], kb + np * (16u * SR * 4u));
#pragma unroll
        for (int m = 0; m < 4; m++)
#pragma unroll
            for (int n = 0; n < 4; n++) mma8(acc[m][n], af[m], bf[n]);
    }
}

#define ACC_ZERO(acc)                                   \
    _Pragma("unroll")                                   \
    for (int a_ = 0; a_ < 4; a_++)                      \
        _Pragma("unroll")                               \
        for (int b_ = 0; b_ < 4; b_++)                  \
            _Pragma("unroll")                           \
            for (int c_ = 0; c_ < 4; c_++) acc[a_][b_][c_] = 0.0f;

// Per-thread ldmatrix address offsets (bytes) within a stage.
#define LDSM_OFFSETS()                                                        \
    const int L_ = tid & 31;                                                  \
    const uint32_t aoff = ((uint32_t)((L_ & 15) + wm * 64) * SR) * 4u +       \
                          (uint32_t)(L_ >> 4) * 16u;                          \
    const uint32_t boff = ((uint32_t)((((L_ >> 4) & 1) * 8) + (L_ & 7) + wn * 32) * SR) * 4u + \
                          (uint32_t)((L_ >> 3) & 1) * 16u;

// Double-buffered mainloop: 1 sync per chunk, STS overlapped with MMA.
#define GEMM_PIPELINE(S, sb, nch, LOADG)                      \
    LOADG(0);                                                 \
    sts_split(S, tid, av, bv);                                \
    __syncthreads();                                          \
    for (int i = 0; i < (nch); i++) {                         \
        bool more_ = (i + 1 < (nch));                         \
        if (more_) LOADG(i + 1);                              \
        mma_block((sb) + (uint32_t)(i & 1) * (STAGE_F * 4u), aoff, boff, acc); \
        if (more_) sts_split((S) + ((i + 1) & 1) * STAGE_F, tid, av, bv); \
        __syncthreads();                                      \
    }

// ---------------- init / scan -------------------------------------------------
__global__ void k_init() {
    int idx = blockIdx.x * 256 + threadIdx.x;
    if (idx < BB * HH) { g_h[idx] = 0.0f; g_c[idx] = 0.0f; }
}
__global__ void k_scan(const int* __restrict__ seq_lens) {
    int tid = threadIdx.x;   // 256
    if (tid == 0) {
        int acc = 0;
        for (int b = 0; b < BB; b++) { g_off[b] = acc; acc += seq_lens[b]; }
        g_nrows = acc;
    }
    if (tid < TT) {
        int c = 0;
        for (int b = 0; b < BB; b++) c += (seq_lens[b] > tid) ? 1 : 0;
        g_nb[tid] = c;
    }
    __syncthreads();
    {
        int b = tid;
        int o = g_off[b], len = seq_lens[b];
        for (int t = 0; t < len; t++) g_rbt[o + t] = (b << 6) | t;
    }
}
__global__ void k_I0(const float* __restrict__ init_t,
                     const float* __restrict__ W_ih) {
    int j = blockIdx.x * 256 + threadIdx.x;   // 4096
    const float* w = W_ih + (size_t)j * (DIN + EE) + DIN;
    float s = 0.0f;
    for (int e = 0; e < EE; e++) s += init_t[e] * w[e];
    g_I0[j] = s;
}

// ================= Phase A (fused): EW (by<64) and XW (by>=64) ================
__global__ __launch_bounds__(256, 2)
void kA(const float* __restrict__ enc, const float* __restrict__ emb,
        const float* __restrict__ W_ih) {
    extern __shared__ float S[];
    const uint32_t sb = (uint32_t)__cvta_generic_to_shared(S);
    const int tid = threadIdx.x;
    const int wid = tid >> 5;
    const int wm  = wid >> 2, wn = wid & 3;
    const int g   = (tid & 31) >> 2, tig = tid & 3;
    const int kq  = tid & 3;
    LDSM_OFFSETS()

    const int bn = blockIdx.x * 128;
    float acc[4][4][4];
    ACC_ZERO(acc)
    float4 av[2], bv[2];

    const bool isE = (blockIdx.y < VV / 128);
    int bm;
    int nch;
    const float* pa[2];
    const float* pb[2];
    if (isE) {
        bm = blockIdx.y * 128;
        nch = EE / BK;
#pragma unroll
        for (int j = 0; j < 2; j++) {
            int row = ((j * 256 + tid) >> 2);
            pa[j] = emb + (size_t)(bm + row) * EE;
            pb[j] = W_ih + (size_t)(bn + row) * (DIN + EE) + DIN;
        }
    } else {
        bm = (blockIdx.y - VV / 128) * 128;
        if (bm >= g_nrows) return;
        nch = DIN / BK;
#pragma unroll
        for (int j = 0; j < 2; j++) {
            int row = ((j * 256 + tid) >> 2);
            int bt = g_rbt[bm + row];
            int b = bt >> 6, t = bt & 63;
            pa[j] = enc + ((size_t)b * TT + t) * DIN;
            pb[j] = W_ih + (size_t)(bn + row) * (DIN + EE);
        }
    }

#define LG(ch)                                                    \
    { int kkb = (ch) * BK + kq * 4;                               \
      _Pragma("unroll")                                           \
      for (int j = 0; j < 2; j++) {                               \
          av[j] = *(const float4*)(pa[j] + kkb);                  \
          bv[j] = *(const float4*)(pb[j] + kkb); } }
    GEMM_PIPELINE(S, sb, nch, LG)
#undef LG

    float* dst = isE ? g_EW : g_XW;
#pragma unroll
    for (int m = 0; m < 4; m++) {
        int lr0 = wm * 64 + m * 16 + g, lr1 = lr0 + 8;
#pragma unroll
        for (int n = 0; n < 4; n++) {
            int col = bn + wn * 32 + n * 8 + 2 * tig;
            *(float2*)&dst[(size_t)(bm + lr0) * FOURH + col] =
                make_float2(acc[m][n][0], acc[m][n][1]);
            *(float2*)&dst[(size_t)(bm + lr1) * FOURH + col] =
                make_float2(acc[m][n][2], acc[m][n][3]);
        }
    }
}

// ================= fused kernel: logits(t) || gates(t+1), PURE GEMM ===========
// Even CTAs = logits(t) partials, odd CTAs = gates(t+1) partials.
// No atomics / combine here — k_cell(t+1) consumes both.
__global__ __launch_bounds__(256, 2)
void k_lg(const float* __restrict__ W_hh,
          const float* __restrict__ lin_W,
          int t) {
    extern __shared__ float S[];
    const uint32_t sbda = (uint32_t)__cvta_generic_to_shared(S);
    const int cta  = blockIdx.x;
    const int kind = cta & 1;          // 1 = gates(t+1), 0 = logits(t)
    const int idx  = cta >> 1;         // 0..255

    const int tid = threadIdx.x;
    const int wid = tid >> 5;
    const int wm  = wid >> 2, wn = wid & 3;
    const int g   = (tid & 31) >> 2, tig = tid & 3;
    const int kq  = tid & 3;
    LDSM_OFFSETS()

    int bm, kbeg, nch, bn, slot;
    const float* Bb;
    if (kind) {
        if (t + 1 >= TT) return;       // last step: no gates half
        const int nbt = g_nb[t + 1];
        int bx_ = idx & 31, by = (idx >> 5) & 3, bz = (idx >> 7) & 1;
        if (nbt > 128) {
            bm = bz * 128; kbeg = by * (HH / 4); nch = (HH / 4) / BK;  // 16
            slot = bz * 4 + by;
        } else {
            bm = 0;
            int ks = by * 2 + bz;
            kbeg = ks * (HH / 8); nch = (HH / 8) / BK;                 // 8
            slot = ks;
        }
        bn = bx_ * 128;
        Bb = W_hh;
    } else {
        const int nbt = g_nb[t];
        const bool split = (nbt <= 128);
        int bx = idx & 63, by = (idx >> 6) & 1, bz = (idx >> 7) & 1;
        if (!split) {
            bm = bz * 128; kbeg = by * (HH / 2); nch = (HH / 2) / BK;  // 32
            slot = bz * 2 + by;
        } else {
            int q = by * 2 + bz;
            bm = 0; kbeg = q * (HH / 4); nch = (HH / 4) / BK;          // 16
            slot = q;
        }
        bn = bx * 128;
        Bb = lin_W;
    }

    const float* pa[2];
    const float* pb[2];
#pragma unroll
    for (int j = 0; j < 2; j++) {
        int row = ((j * 256 + tid) >> 2);
        pa[j] = g_h + (size_t)(bm + row) * HH + kbeg;
        pb[j] = Bb + (size_t)(bn + row) * HH + kbeg;
    }

    float acc[4][4][4];
    ACC_ZERO(acc)
    float4 av[2], bv[2];
#define LG(ch)                                                    \
    { int kkb = (ch) * BK + kq * 4;                               \
      _Pragma("unroll")                                           \
      for (int j = 0; j < 2; j++) {                               \
          av[j] = *(const float4*)(pa[j] + kkb);                  \
          bv[j] = *(const float4*)(pb[j] + kkb); } }
    GEMM_PIPELINE(S, sbda, nch, LG)
#undef LG

    if (kind) {
        // gates: partial to g_P[slot]
#pragma unroll
        for (int m = 0; m < 4; m++) {
            int lr0 = wm * 64 + m * 16 + g, lr1 = lr0 + 8;
#pragma unroll
            for (int n = 0; n < 4; n++) {
                int col = bn + wn * 32 + n * 8 + 2 * tig;
                *(float2*)&g_P[slot][lr0][col] =
                    make_float2(acc[m][n][0], acc[m][n][1]);
                *(float2*)&g_P[slot][lr1][col] =
                    make_float2(acc[m][n][2], acc[m][n][3]);
            }
        }
    } else {
        // logits: partial to g_logP[slot]
#pragma unroll
        for (int half = 0; half < 2; half++)
#pragma unroll
            for (int mt = 0; mt < 4; mt++) {
                int lr = wm * 64 + mt * 16 + g + half * 8;
#pragma unroll
                for (int nt = 0; nt < 4; nt++) {
                    int col = bn + wn * 32 + nt * 8 + 2 * tig;
                    *(float2*)&g_logP[slot][lr][col] =
                        make_float2(acc[mt][nt][half * 2], acc[mt][nt][half * 2 + 1]);
                }
            }
    }
}

// ================= k_cell: logits(tlog) combine+store+argmax, then cell(tcell)
// One CTA per batch row b. Fixed-tree combine (bit-identical to prior winner).
__global__ void k_cell(const float* __restrict__ lin_b,
                       const float* __restrict__ b_ih,
                       const float* __restrict__ b_hh,
                       const int* __restrict__ seq_lens,
                       float* __restrict__ out,
                       int tlog, int tcell) {
    const int b   = blockIdx.x;
    const int tid = threadIdx.x;   // 256
    const int lane = tid & 31, w = tid >> 5;
    __shared__ float sv[8];
    __shared__ int   si[8];
    __shared__ int   sbest;

    // ---- logits combine / ragged store / argmax for step tlog ----
    if (tlog >= 0) {
        const int nbt = g_nb[tlog];
        const bool split = (nbt <= 128);
        const int len = seq_lens[b];
        const bool wr = (tlog < len);
        float* orow = out + (size_t)(g_off[b] + tlog) * VV;

        float bv = -3.4e38f;
        int   bi = 0x7fffffff;
        if (!split || b < 128) {
            const int lr = b & 127;
            const int s0 = (!split && b >= 128) ? 2 : 0;
            const int c0 = tid * 32;
#pragma unroll
            for (int cc = 0; cc < 32; cc += 4) {
                int col = c0 + cc;
                float4 v;
                if (!split) {
                    float4 p0 = __ldcg((const float4*)&g_logP[s0][lr][col]);
                    float4 p1 = __ldcg((const float4*)&g_logP[s0 + 1][lr][col]);
                    v.x = p0.x + p1.x; v.y = p0.y + p1.y;
                    v.z = p0.z + p1.z; v.w = p0.w + p1.w;
                } else {
                    float4 p0 = __ldcg((const float4*)&g_logP[0][lr][col]);
                    float4 p1 = __ldcg((const float4*)&g_logP[1][lr][col]);
                    float4 p2 = __ldcg((const float4*)&g_logP[2][lr][col]);
                    float4 p3 = __ldcg((const float4*)&g_logP[3][lr][col]);
                    v.x = (p0.x + p1.x) + (p2.x + p3.x);
                    v.y = (p0.y + p1.y) + (p2.y + p3.y);
                    v.z = (p0.z + p1.z) + (p2.z + p3.z);
                    v.w = (p0.w + p1.w) + (p2.w + p3.w);
                }
                float4 lb = *(const float4*)&lin_b[col];
                v.x += lb.x; v.y += lb.y; v.z += lb.z; v.w += lb.w;
                if (wr) *(float4*)&orow[col] = v;
                if (v.x > bv) { bv = v.x; bi = col; }
                if (v.y > bv) { bv = v.y; bi = col + 1; }
                if (v.z > bv) { bv = v.z; bi = col + 2; }
                if (v.w > bv) { bv = v.w; bi = col + 3; }
            }
        }
        // block argmax reduce (lower index wins ties)
#pragma unroll
        for (int off = 16; off; off >>= 1) {
            float ov = __shfl_xor_sync(0xffffffffu, bv, off);
            int   oi = __shfl_xor_sync(0xffffffffu, bi, off);
            if (ov > bv || (ov == bv && oi < bi)) { bv = ov; bi = oi; }
        }
        if (lane == 0) { sv[w] = bv; si[w] = bi; }
        __syncthreads();
        if (tid == 0) {
            float vb = sv[0]; int ib = si[0];
#pragma unroll
            for (int q = 1; q < 8; q++)
                if (sv[q] > vb || (sv[q] == vb && si[q] < ib)) { vb = sv[q]; ib = si[q]; }
            sbest = ib;
        }
        __syncthreads();
    }

    // ---- cell update for step tcell ----
    if (tcell >= TT) return;
    const int nbt = g_nb[tcell];
    if (nbt <= 128 && b >= 128) return;
    if (tcell >= seq_lens[b]) return;

    const int j = tid * 4;   // 256 threads x 4 = H
    float4 gate[4];
#pragma unroll
    for (int q = 0; q < 4; q++) {
        int jj = q * 1024 + j;
        float4 r;
        if (tcell == 0) {
            r = make_float4(0.f, 0.f, 0.f, 0.f);
        } else if (nbt > 128) {
            int s0 = (b >> 7) * 4, lr = b & 127;
            float4 p0 = *(const float4*)&g_P[s0][lr][jj];
            float4 p1 = *(const float4*)&g_P[s0 + 1][lr][jj];
            float4 p2 = *(const float4*)&g_P[s0 + 2][lr][jj];
            float4 p3 = *(const float4*)&g_P[s0 + 3][lr][jj];
            r.x = (p0.x + p1.x) + (p2.x + p3.x);
            r.y = (p0.y + p1.y) + (p2.y + p3.y);
            r.z = (p0.z + p1.z) + (p2.z + p3.z);
            r.w = (p0.w + p1.w) + (p2.w + p3.w);
        } else {
            float4 p0 = *(const float4*)&g_P[0][b][jj];
            float4 p1 = *(const float4*)&g_P[1][b][jj];
            float4 p2 = *(const float4*)&g_P[2][b][jj];
            float4 p3 = *(const float4*)&g_P[3][b][jj];
            float4 p4 = *(const float4*)&g_P[4][b][jj];
            float4 p5 = *(const float4*)&g_P[5][b][jj];
            float4 p6 = *(const float4*)&g_P[6][b][jj];
            float4 p7 = *(const float4*)&g_P[7][b][jj];
            r.x = ((p0.x + p1.x) + (p2.x + p3.x)) + ((p4.x + p5.x) + (p6.x + p7.x));
            r.y = ((p0.y + p1.y) + (p2.y + p3.y)) + ((p4.y + p5.y) + (p6.y + p7.y));
            r.z = ((p0.z + p1.z) + (p2.z + p3.z)) + ((p4.z + p5.z) + (p6.z + p7.z));
            r.w = ((p0.w + p1.w) + (p2.w + p3.w)) + ((p4.w + p5.w) + (p6.w + p7.w));
        }
        gate[q] = r;
    }
    const float* XW = g_XW + (size_t)(g_off[b] + tcell) * FOURH;
    const float* EW = (tcell == 0) ? g_I0 : g_EW + (size_t)sbest * FOURH;
    size_t cidx = (size_t)b * HH + j;
    float4 cc = *(const float4*)&g_c[cidx];
    float4 ho, co;
#pragma unroll
    for (int e = 0; e < 4; e++) {
        int je = j + e;
        float gi = (&gate[0].x)[e] + XW[je]        + EW[je]        + b_ih[je]        + b_hh[je];
        float gf = (&gate[1].x)[e] + XW[1024 + je] + EW[1024 + je] + b_ih[1024 + je] + b_hh[1024 + je];
        float gg = (&gate[2].x)[e] + XW[2048 + je] + EW[2048 + je] + b_ih[2048 + je] + b_hh[2048 + je];
        float go = (&gate[3].x)[e] + XW[3072 + je] + EW[3072 + je] + b_ih[3072 + je] + b_hh[3072 + je];
        float c = sigm(gf) * (&cc.x)[e] + sigm(gi) * tanhf(gg);
        float h = sigm(go) * tanhf(c);
        (&co.x)[e] = c;
        (&ho.x)[e] = h;
    }
    *(float4*)&g_c[cidx] = co;
    *(float4*)&g_h[cidx] = ho;
}

// ---------------- launch ------------------------------------------------------
extern "C" void kernel_launch(void* const* d_in, const int* in_sizes, int n_in,
                              void* d_out, int out_size) {
    const float* enc      = (const float*)d_in[0];
    const float* emb      = (const float*)d_in[1];
    const float* init_t   = (const float*)d_in[2];
    const float* W_ih     = (const float*)d_in[3];
    const float* W_hh     = (const float*)d_in[4];
    const float* b_ih     = (const float*)d_in[5];
    const float* b_hh     = (const float*)d_in[6];
    const float* lin_W    = (const float*)d_in[7];
    const float* lin_b    = (const float*)d_in[8];
    const int*   seq_lens = (const int*)d_in[9];
    float*       out      = (float*)d_out;

    cudaFuncSetAttribute(kA,   cudaFuncAttributeMaxDynamicSharedMemorySize, SMEM_B);
    cudaFuncSetAttribute(k_lg, cudaFuncAttributeMaxDynamicSharedMemorySize, SMEM_B);

    k_init<<<(BB * HH + 255) / 256, 256>>>();
    k_scan<<<1, 256>>>(seq_lens);
    k_I0<<<FOURH / 256, 256>>>(init_t, W_ih);
    kA<<<dim3(32, VV / 128 + (BB * TT) / 128), 256, SMEM_B>>>(enc, emb, W_ih);

    // t = 0: no logits yet (tlog=-1); cell(0) with zero gates (h(0)==0).
    k_cell<<<BB, 256>>>(lin_b, b_ih, b_hh, seq_lens, out, -1, 0);

    for (int t = 0; t < TT - 1; t++) {
        // pure-GEMM fused kernel: logits(t) partials || gates(t+1) partials
        k_lg<<<512, 256, SMEM_B>>>(W_hh, lin_W, t);
        // combine+store+argmax for logits(t), then cell(t+1)
        k_cell<<<BB, 256>>>(lin_b, b_ih, b_hh, seq_lens, out, t, t + 1);
    }
    // final step: logits(TT-1) partials only, then combine-only k_cell
    k_lg<<<512, 256, SMEM_B>>>(W_hh, lin_W, TT - 1);
    k_cell<<<BB, 256>>>(lin_b, b_ih, b_hh, seq_lens, out, TT - 1, TT);
}